// round 9
// baseline (speedup 1.0000x reference)
#include <cuda_runtime.h>
#include <cuda_bf16.h>
#include <cstdint>

#define SEQ   2048
#define BATCH 32
#define DIM   256
#define HEADS 4
#define MROWS (SEQ*BATCH)      /* 65536 */
#define NBUF  (MROWS*DIM)      /* 16777216 floats = 64MB */

// Scratch: Q ping/pong, K ping/pong, V ping/pong, W ping/pong  (8 x 64MB)
__device__ float g_buf[8][NBUF];
__device__ float g_stats[2*DIM];
__device__ float g_bnscale[DIM];
__device__ float g_bnshift[DIM];
__device__ float g_headout[HEADS*BATCH*DIM];
__device__ float g_x0[BATCH*HEADS*DIM];
__device__ float g_x1[BATCH*DIM];
__device__ float g_x2[BATCH*DIM];
// pre-split weights: 5 families (wq,wk,wv,wl1,wl2) x 4 heads x 256x256
__device__ __nv_bfloat16 g_wh[5*HEADS*DIM*DIM];
__device__ __nv_bfloat16 g_wl[5*HEADS*DIM*DIM];

// ===========================================================================
// helpers
// ===========================================================================
__device__ __forceinline__ uint32_t smem_u32(const void* p) {
    uint32_t a;
    asm("{ .reg .u64 t; cvta.to.shared.u64 t, %1; cvt.u32.u64 %0, t; }" : "=r"(a) : "l"(p));
    return a;
}
__device__ __forceinline__ void ldsm4(uint32_t* r, uint32_t addr) {
    asm volatile("ldmatrix.sync.aligned.m8n8.x4.shared.b16 {%0,%1,%2,%3}, [%4];"
                 : "=r"(r[0]), "=r"(r[1]), "=r"(r[2]), "=r"(r[3]) : "r"(addr));
}
__device__ __forceinline__ void mma_bf16(float* c, const uint32_t* a, uint32_t b0, uint32_t b1) {
    asm volatile("mma.sync.aligned.m16n8k16.row.col.f32.bf16.bf16.f32 "
                 "{%0,%1,%2,%3}, {%4,%5,%6,%7}, {%8,%9}, {%0,%1,%2,%3};"
                 : "+f"(c[0]), "+f"(c[1]), "+f"(c[2]), "+f"(c[3])
                 : "r"(a[0]), "r"(a[1]), "r"(a[2]), "r"(a[3]), "r"(b0), "r"(b1));
}
__device__ __forceinline__ uint32_t pack_bf16(float x, float y) {
    __nv_bfloat162 t = __floats2bfloat162_rn(x, y);
    return *(uint32_t*)&t;
}
__device__ __forceinline__ void split_bf16(float f, float& hi, float& lo) {
    __nv_bfloat16 bh = __float2bfloat16_rn(f);
    hi = __bfloat162float(bh);
    lo = f - hi;
}
__device__ __forceinline__ void cpasync16(uint32_t dst, const void* src) {
    asm volatile("cp.async.cg.shared.global [%0], [%1], 16;" :: "r"(dst), "l"(src));
}
__device__ __forceinline__ void cpasync_commit() { asm volatile("cp.async.commit_group;"); }
__device__ __forceinline__ void cpasync_wait0()  { asm volatile("cp.async.wait_group 0;" ::: "memory"); }

// ===========================================================================
// weight pre-split: fp32 -> (bf16 hi, bf16 lo)
// ===========================================================================
struct WPtrs { const float* p[5]; };
__global__ void wsplit_kernel(WPtrs wp, __nv_bfloat16* __restrict__ wh,
                              __nv_bfloat16* __restrict__ wl)
{
    const int i = blockIdx.x * blockDim.x + threadIdx.x;
    const int fam = i >> 18;
    const int off = i & 262143;
    float v = wp.p[fam][off];
    __nv_bfloat16 h = __float2bfloat16_rn(v);
    wh[i] = h;
    wl[i] = __float2bfloat16_rn(v - __bfloat162float(h));
}

// ===========================================================================
// bf16-split TC GEMM: C[M,256] = op(A)[M,256] @ W[256,256]^T + bias
//   op(A)=A (BNRELU=false) | relu(A*bnsc[k]+bnsh[k]) (BNRELU=true)
// B from pre-split bf16 weights via cp.async (identical tile for all CTAs
// -> L2-resident).
// CTA 128x256 (N = full width), 8 warps 2Mx4N, warp tile 64x64, BK=16,
// 2-stage pipeline. 64 B smem read per HMMA (2x better than 128x128).
// Stage layout (48B row stride): Ah+0 Al+6144 Bh+12288 Bl+24576 ; 36864B.
// ===========================================================================
#define STAGE_B 36864
#define SMEM_TOT (2*STAGE_B)

template<bool BNRELU>
__global__ __launch_bounds__(256, 1)
void mma_gemm_kernel(const float* __restrict__ A,
                     const __nv_bfloat16* __restrict__ Wh,
                     const __nv_bfloat16* __restrict__ Wl,
                     const float* __restrict__ bias,
                     const float* __restrict__ bnsc, const float* __restrict__ bnsh,
                     float* __restrict__ C)
{
    extern __shared__ char smem[];
    const uint32_t sb = smem_u32(smem);

    const int tid  = threadIdx.x;
    const int lane = tid & 31;
    const int wid  = tid >> 5;
    const int warpM = wid >> 2;          // 0..1 -> 64 rows
    const int warpN = wid & 3;           // 0..3 -> 64 cols
    const int blockM = blockIdx.x * 128;

    const uint32_t aoff = (uint32_t)((warpM * 64 + (lane & 15)) * 48 + (lane >> 4) * 16);
    const uint32_t boff = (uint32_t)((warpN * 64 + (lane & 7) + ((lane >> 4) & 1) * 8) * 48
                                     + ((lane >> 3) & 1) * 16);

    // A fp32 producer: idx = tid + j*256 -> row = idx>>2 (0..127), q = idx&3
    const int prow = tid >> 2;
    const int pq   = tid & 3;
    // B cp.async producer: one row per thread (256 rows), 4 cp.async each
    const int brow = tid;

    float acc[4][8][4];
    #pragma unroll
    for (int i = 0; i < 4; i++)
        #pragma unroll
        for (int j = 0; j < 8; j++)
            #pragma unroll
            for (int r = 0; r < 4; r++) acc[i][j][r] = 0.f;

    auto issue_b = [&](uint32_t stage, int kt) {
        const uint32_t dh = stage + 12288u + (uint32_t)(brow * 48);
        const uint32_t dl = stage + 24576u + (uint32_t)(brow * 48);
        const int so = brow * DIM + kt;
        cpasync16(sb + dh,      Wh + so);
        cpasync16(sb + dh + 16, Wh + so + 8);
        cpasync16(sb + dl,      Wl + so);
        cpasync16(sb + dl + 16, Wl + so + 8);
    };
    auto ldg_a = [&](int kt, float4* g) {
        #pragma unroll
        for (int j = 0; j < 2; j++)
            g[j] = *(const float4*)&A[(blockM + prow + j * 64) * DIM + kt + pq * 4];
    };
    auto st_a = [&](uint32_t stage, int kt, const float4* g) {
        #pragma unroll
        for (int j = 0; j < 2; j++) {
            float4 a = g[j];
            if (BNRELU) {
                const float4 sc = *(const float4*)&bnsc[kt + pq * 4];
                const float4 sh = *(const float4*)&bnsh[kt + pq * 4];
                a.x = fmaxf(fmaf(a.x, sc.x, sh.x), 0.f);
                a.y = fmaxf(fmaf(a.y, sc.y, sh.y), 0.f);
                a.z = fmaxf(fmaf(a.z, sc.z, sh.z), 0.f);
                a.w = fmaxf(fmaf(a.w, sc.w, sh.w), 0.f);
            }
            float h0,l0,h1,l1,h2,l2,h3,l3;
            split_bf16(a.x, h0, l0); split_bf16(a.y, h1, l1);
            split_bf16(a.z, h2, l2); split_bf16(a.w, h3, l3);
            const uint32_t dst = stage + (uint32_t)((prow + j * 64) * 48 + pq * 8);
            *(uint2*)(smem + dst)        = make_uint2(pack_bf16(h0, h1), pack_bf16(h2, h3));
            *(uint2*)(smem + dst + 6144) = make_uint2(pack_bf16(l0, l1), pack_bf16(l2, l3));
        }
    };
    auto compute_sub = [&](uint32_t base) {
        // A-h fragments (reused for term1+term2; array later reused for A-l)
        uint32_t af[4][4];
        #pragma unroll
        for (int mt = 0; mt < 4; mt++)
            ldsm4(af[mt], sb + base + aoff + (uint32_t)(mt * 768));
        // B-h fragments (live through term1 + term3)
        uint32_t bh[8][2];
        #pragma unroll
        for (int j = 0; j < 4; j++) {
            uint32_t t[4];
            ldsm4(t, sb + base + 12288 + boff + (uint32_t)(j * 768));
            bh[2*j][0] = t[0]; bh[2*j][1] = t[1];
            bh[2*j+1][0] = t[2]; bh[2*j+1][1] = t[3];
        }
        #pragma unroll
        for (int mt = 0; mt < 4; mt++)
            #pragma unroll
            for (int nt = 0; nt < 8; nt++)
                mma_bf16(acc[mt][nt], af[mt], bh[nt][0], bh[nt][1]);   // ah*bh
        // B-l fragments (die after term2)
        {
            uint32_t bl[8][2];
            #pragma unroll
            for (int j = 0; j < 4; j++) {
                uint32_t t[4];
                ldsm4(t, sb + base + 24576 + boff + (uint32_t)(j * 768));
                bl[2*j][0] = t[0]; bl[2*j][1] = t[1];
                bl[2*j+1][0] = t[2]; bl[2*j+1][1] = t[3];
            }
            #pragma unroll
            for (int mt = 0; mt < 4; mt++)
                #pragma unroll
                for (int nt = 0; nt < 8; nt++)
                    mma_bf16(acc[mt][nt], af[mt], bl[nt][0], bl[nt][1]); // ah*bl
        }
        // A-l reuses af storage
        #pragma unroll
        for (int mt = 0; mt < 4; mt++)
            ldsm4(af[mt], sb + base + 6144 + aoff + (uint32_t)(mt * 768));
        #pragma unroll
        for (int mt = 0; mt < 4; mt++)
            #pragma unroll
            for (int nt = 0; nt < 8; nt++)
                mma_bf16(acc[mt][nt], af[mt], bh[nt][0], bh[nt][1]);   // al*bh
    };

    // ---- prologue: stage 0 ----
    issue_b(0, 0);
    cpasync_commit();
    {
        float4 g0[2];
        ldg_a(0, g0);
        st_a(0, 0, g0);
    }
    cpasync_wait0();
    __syncthreads();

    // ---- mainloop: 16 k-chunks, 2-stage ----
    #pragma unroll 1
    for (int c = 0; c < 16; c++) {
        const uint32_t cur = (uint32_t)(c & 1) * STAGE_B;
        const uint32_t nxt = (uint32_t)((c + 1) & 1) * STAGE_B;
        float4 gA[2];
        if (c < 15) {
            const int kt = (c + 1) * 16;
            issue_b(nxt, kt);
            cpasync_commit();
            ldg_a(kt, gA);
        }
        compute_sub(cur);
        if (c < 15) st_a(nxt, (c + 1) * 16, gA);
        cpasync_wait0();
        __syncthreads();
    }

    // ---- epilogue: bias add + direct stores ----
    #pragma unroll
    for (int nt = 0; nt < 8; nt++) {
        const int n0 = warpN * 64 + nt * 8 + (lane & 3) * 2;
        const float2 bb = *(const float2*)&bias[n0];
        #pragma unroll
        for (int mt = 0; mt < 4; mt++) {
            const int m0 = blockM + warpM * 64 + mt * 16 + (lane >> 2);
            float2 o0 = make_float2(acc[mt][nt][0] + bb.x, acc[mt][nt][1] + bb.y);
            float2 o1 = make_float2(acc[mt][nt][2] + bb.x, acc[mt][nt][3] + bb.y);
            *(float2*)&C[m0 * DIM + n0]       = o0;
            *(float2*)&C[(m0 + 8) * DIM + n0] = o1;
        }
    }
}

// ---------------------------------------------------------------------------
// W = K - Q, plus per-channel sum / sumsq  (thread = channel, block strides rows)
__global__ void sub_stats_kernel(const float* __restrict__ Kx, const float* __restrict__ Qx,
                                 float* __restrict__ Wout, float* __restrict__ stats)
{
    const int d = threadIdx.x;
    float s1 = 0.f, s2 = 0.f;
    for (int r = blockIdx.x; r < MROWS; r += gridDim.x) {
        const int i = r * DIM + d;
        float w = Kx[i] - Qx[i];
        Wout[i] = w;
        s1 += w; s2 += w * w;
    }
    atomicAdd(&stats[d], s1);
    atomicAdd(&stats[DIM + d], s2);
}

__global__ void stats_kernel(const float* __restrict__ X, float* __restrict__ stats)
{
    const int d = threadIdx.x;
    float s1 = 0.f, s2 = 0.f;
    for (int r = blockIdx.x; r < MROWS; r += gridDim.x) {
        float w = X[r * DIM + d];
        s1 += w; s2 += w * w;
    }
    atomicAdd(&stats[d], s1);
    atomicAdd(&stats[DIM + d], s2);
}

// bn_finalize: consume stats -> (scale, shift), then re-zero stats buffer.
__global__ void bn_finalize_kernel(float* __restrict__ stats,
                                   const float* __restrict__ gamma,
                                   const float* __restrict__ beta,
                                   float* __restrict__ sc, float* __restrict__ sh)
{
    const int d = threadIdx.x;
    const float inv = 1.f / (float)MROWS;
    float mean = stats[d] * inv;
    float var  = stats[DIM + d] * inv - mean * mean;
    float r    = rsqrtf(var + 1e-5f);
    float s    = gamma[d] * r;
    sc[d] = s;
    sh[d] = beta[d] - mean * s;
    stats[d] = 0.f;
    stats[DIM + d] = 0.f;
}

// ---------------------------------------------------------------------------
__global__ void softmax_wsum_kernel(const float* __restrict__ Wm,
                                    const float* __restrict__ V,
                                    float* __restrict__ out)
{
    const int b    = blockIdx.x >> 3;
    const int lane = threadIdx.x & 31;
    const int w    = threadIdx.x >> 5;
    const int d    = ((blockIdx.x & 7) << 5) + lane;
    const int BD   = BATCH * DIM;
    const int base = b * DIM + d;

    const float NEG_INF = __int_as_float(0xff800000u);
    float m = NEG_INF, Z = 0.f, acc = 0.f;
    const int s0 = w * (SEQ / 8);
    for (int s = s0; s < s0 + SEQ / 8; s++) {
        const int idx = s * BD + base;
        float x  = Wm[idx];
        float vv = V[idx];
        if (x > m) {
            float c = __expf(m - x);
            Z   = Z * c + 1.f;
            acc = acc * c + vv;
            m = x;
        } else {
            float e = __expf(x - m);
            Z   += e;
            acc += e * vv;
        }
    }
    __shared__ float sm[8][32], sz[8][32], sa[8][32];
    sm[w][lane] = m; sz[w][lane] = Z; sa[w][lane] = acc;
    __syncthreads();
    if (w == 0) {
        float M = NEG_INF;
        #pragma unroll
        for (int j = 0; j < 8; j++) M = fmaxf(M, sm[j][lane]);
        float Zt = 0.f, At = 0.f;
        #pragma unroll
        for (int j = 0; j < 8; j++) {
            float c = __expf(sm[j][lane] - M);
            Zt += sz[j][lane] * c;
            At += sa[j][lane] * c;
        }
        out[base] = At / Zt;
    }
}

__global__ void pack_kernel(const float* __restrict__ ho, float* __restrict__ x0)
{
    const int i = blockIdx.x * blockDim.x + threadIdx.x;
    const int b = i >> 10;
    const int c = i & 1023;
    const int h = c >> 8;
    const int d = c & 255;
    x0[i] = ho[h * (BATCH * DIM) + b * DIM + d];
}

template<bool RELU, int K>
__global__ void smallgemm_kernel(const float* __restrict__ X, const float* __restrict__ Wt,
                                 const float* __restrict__ bias, float* __restrict__ C)
{
    __shared__ float Xs[32][257];
    __shared__ float Ws[8][257];
    const int tid = threadIdx.x;
    const int b  = tid & 31;
    const int nl = tid >> 5;
    const int n  = blockIdx.x * 8 + nl;
    float acc = 0.f;
    for (int k0 = 0; k0 < K; k0 += 256) {
        #pragma unroll
        for (int j = 0; j < 8; j++)
            Ws[j][tid] = Wt[(blockIdx.x * 8 + j) * K + k0 + tid];
        #pragma unroll
        for (int j = 0; j < 32; j++)
            Xs[j][tid] = X[j * K + k0 + tid];
        __syncthreads();
        #pragma unroll 8
        for (int kk = 0; kk < 256; kk++) acc += Xs[b][kk] * Ws[nl][kk];
        __syncthreads();
    }
    float val = acc + bias[n];
    if (RELU) val = fmaxf(val, 0.f);
    C[b * DIM + n] = val;
}

// ---------------------------------------------------------------------------
extern "C" void kernel_launch(void* const* d_in, const int* in_sizes, int n_in,
                              void* d_out, int out_size)
{
    const float* q   = (const float*)d_in[0];
    const float* k   = (const float*)d_in[1];
    const float* v   = (const float*)d_in[2];
    const float* wq  = (const float*)d_in[3];
    const float* bq  = (const float*)d_in[4];
    const float* wk  = (const float*)d_in[5];
    const float* bk  = (const float*)d_in[6];
    const float* wv  = (const float*)d_in[7];
    const float* bv  = (const float*)d_in[8];
    const float* g1  = (const float*)d_in[9];
    const float* be1 = (const float*)d_in[10];
    const float* wl1 = (const float*)d_in[11];
    const float* bl1 = (const float*)d_in[12];
    const float* g2  = (const float*)d_in[13];
    const float* be2 = (const float*)d_in[14];
    const float* wl2 = (const float*)d_in[15];
    const float* bl2 = (const float*)d_in[16];
    const float* mw0 = (const float*)d_in[17];
    const float* mb0 = (const float*)d_in[18];
    const float* mw1 = (const float*)d_in[19];
    const float* mb1 = (const float*)d_in[20];
    const float* mw2 = (const float*)d_in[21];
    const float* mb2 = (const float*)d_in[22];

    float* buf;   cudaGetSymbolAddress((void**)&buf,   g_buf);
    float* stats; cudaGetSymbolAddress((void**)&stats, g_stats);
    float* bnsc;  cudaGetSymbolAddress((void**)&bnsc,  g_bnscale);
    float* bnsh;  cudaGetSymbolAddress((void**)&bnsh,  g_bnshift);
    float* ho;    cudaGetSymbolAddress((void**)&ho,    g_headout);
    float* x0;    cudaGetSymbolAddress((void**)&x0,    g_x0);
    float* x1;    cudaGetSymbolAddress((void**)&x1,    g_x1);
    float* x2;    cudaGetSymbolAddress((void**)&x2,    g_x2);
    __nv_bfloat16* wh; cudaGetSymbolAddress((void**)&wh, g_wh);
    __nv_bfloat16* wl; cudaGetSymbolAddress((void**)&wl, g_wl);

    cudaFuncSetAttribute(mma_gemm_kernel<false>, cudaFuncAttributeMaxDynamicSharedMemorySize, SMEM_TOT);
    cudaFuncSetAttribute(mma_gemm_kernel<true>,  cudaFuncAttributeMaxDynamicSharedMemorySize, SMEM_TOT);

    float* Qb[2] = { buf + (size_t)0*NBUF, buf + (size_t)1*NBUF };
    float* Kb[2] = { buf + (size_t)2*NBUF, buf + (size_t)3*NBUF };
    float* Vb[2] = { buf + (size_t)4*NBUF, buf + (size_t)5*NBUF };
    float* Wa    =   buf + (size_t)6*NBUF;
    float* Wb    =   buf + (size_t)7*NBUF;

    // split all weights once per replay
    WPtrs wp; wp.p[0] = wq; wp.p[1] = wk; wp.p[2] = wv; wp.p[3] = wl1; wp.p[4] = wl2;
    wsplit_kernel<<<5 * HEADS * DIM * DIM / 256, 256>>>(wp, wh, wl);

    const int WSZ = DIM * DIM;
    dim3 gg(MROWS / 128);              // 512 CTAs, N covered fully per CTA

    const float* Qc = q; const float* Kc = k; const float* Vc = v;
    for (int i = 0; i < HEADS; i++) {
        float* Qn = Qb[i & 1]; float* Kn = Kb[i & 1]; float* Vn = Vb[i & 1];
        const __nv_bfloat16 *qh = wh + (0*HEADS+i)*WSZ, *ql = wl + (0*HEADS+i)*WSZ;
        const __nv_bfloat16 *kh = wh + (1*HEADS+i)*WSZ, *kl = wl + (1*HEADS+i)*WSZ;
        const __nv_bfloat16 *vh = wh + (2*HEADS+i)*WSZ, *vl = wl + (2*HEADS+i)*WSZ;
        const __nv_bfloat16 *l1h= wh + (3*HEADS+i)*WSZ, *l1l= wl + (3*HEADS+i)*WSZ;
        const __nv_bfloat16 *l2h= wh + (4*HEADS+i)*WSZ, *l2l= wl + (4*HEADS+i)*WSZ;

        mma_gemm_kernel<false><<<gg, 256, SMEM_TOT>>>(Qc, qh, ql, bq + i*DIM, nullptr, nullptr, Qn);
        mma_gemm_kernel<false><<<gg, 256, SMEM_TOT>>>(Kc, kh, kl, bk + i*DIM, nullptr, nullptr, Kn);
        mma_gemm_kernel<false><<<gg, 256, SMEM_TOT>>>(Vc, vh, vl, bv + i*DIM, nullptr, nullptr, Vn);

        sub_stats_kernel<<<4096, DIM>>>(Kn, Qn, Wa, stats);
        bn_finalize_kernel<<<1, DIM>>>(stats, g1 + i*DIM, be1 + i*DIM, bnsc, bnsh);

        mma_gemm_kernel<true><<<gg, 256, SMEM_TOT>>>(Wa, l1h, l1l, bl1 + i*DIM, bnsc, bnsh, Wb);

        stats_kernel<<<4096, DIM>>>(Wb, stats);
        bn_finalize_kernel<<<1, DIM>>>(stats, g2 + i*DIM, be2 + i*DIM, bnsc, bnsh);

        mma_gemm_kernel<true><<<gg, 256, SMEM_TOT>>>(Wb, l2h, l2l, bl2 + i*DIM, bnsc, bnsh, Wa);

        softmax_wsum_kernel<<<BATCH * (DIM / 32), 256>>>(Wa, Vn, ho + i*BATCH*DIM);

        Qc = Qn; Kc = Kn; Vc = Vn;
    }

    pack_kernel<<<32, 1024>>>(ho, x0);
    smallgemm_kernel<true,  HEADS*DIM><<<DIM / 8, 256>>>(x0, mw0, mb0, x1);
    smallgemm_kernel<true,  DIM      ><<<DIM / 8, 256>>>(x1, mw1, mb1, x2);
    smallgemm_kernel<false, DIM      ><<<DIM / 8, 256>>>(x2, mw2, mb2, (float*)d_out);
}

// round 10
// speedup vs baseline: 1.8933x; 1.8933x over previous
#include <cuda_runtime.h>
#include <cuda_bf16.h>
#include <cstdint>

#define SEQ   2048
#define BATCH 32
#define DIM   256
#define HEADS 4
#define MROWS (SEQ*BATCH)      /* 65536 */
#define NBUF  (MROWS*DIM)      /* 16777216 floats = 64MB */

// Scratch: Q ping/pong, K ping/pong, V ping/pong, W ping/pong  (8 x 64MB)
__device__ float g_buf[8][NBUF];
__device__ float g_stats[2*DIM];
__device__ float g_bnscale[DIM];
__device__ float g_bnshift[DIM];
__device__ float g_headout[HEADS*BATCH*DIM];
__device__ float g_x0[BATCH*HEADS*DIM];
__device__ float g_x1[BATCH*DIM];
__device__ float g_x2[BATCH*DIM];
// pre-split weights: 5 families (wq,wk,wv,wl1,wl2) x 4 heads x 256x256
__device__ __nv_bfloat16 g_wh[5*HEADS*DIM*DIM];
__device__ __nv_bfloat16 g_wl[5*HEADS*DIM*DIM];

// ===========================================================================
// helpers
// ===========================================================================
__device__ __forceinline__ uint32_t smem_u32(const void* p) {
    uint32_t a;
    asm("{ .reg .u64 t; cvta.to.shared.u64 t, %1; cvt.u32.u64 %0, t; }" : "=r"(a) : "l"(p));
    return a;
}
__device__ __forceinline__ void ldsm4(uint32_t* r, uint32_t addr) {
    asm volatile("ldmatrix.sync.aligned.m8n8.x4.shared.b16 {%0,%1,%2,%3}, [%4];"
                 : "=r"(r[0]), "=r"(r[1]), "=r"(r[2]), "=r"(r[3]) : "r"(addr));
}
__device__ __forceinline__ void mma_bf16(float* c, const uint32_t* a, uint32_t b0, uint32_t b1) {
    asm volatile("mma.sync.aligned.m16n8k16.row.col.f32.bf16.bf16.f32 "
                 "{%0,%1,%2,%3}, {%4,%5,%6,%7}, {%8,%9}, {%0,%1,%2,%3};"
                 : "+f"(c[0]), "+f"(c[1]), "+f"(c[2]), "+f"(c[3])
                 : "r"(a[0]), "r"(a[1]), "r"(a[2]), "r"(a[3]), "r"(b0), "r"(b1));
}
__device__ __forceinline__ uint32_t pack_bf16(float x, float y) {
    __nv_bfloat162 t = __floats2bfloat162_rn(x, y);
    return *(uint32_t*)&t;
}
__device__ __forceinline__ void split_bf16(float f, float& hi, float& lo) {
    __nv_bfloat16 bh = __float2bfloat16_rn(f);
    hi = __bfloat162float(bh);
    lo = f - hi;
}
__device__ __forceinline__ void cpasync16(uint32_t dst, const void* src) {
    asm volatile("cp.async.cg.shared.global [%0], [%1], 16;" :: "r"(dst), "l"(src));
}
__device__ __forceinline__ void cpasync_commit() { asm volatile("cp.async.commit_group;"); }
__device__ __forceinline__ void cpasync_wait0()  { asm volatile("cp.async.wait_group 0;" ::: "memory"); }

// ===========================================================================
// weight pre-split: fp32 -> (bf16 hi, bf16 lo)
// ===========================================================================
struct WPtrs { const float* p[5]; };
__global__ void wsplit_kernel(WPtrs wp, __nv_bfloat16* __restrict__ wh,
                              __nv_bfloat16* __restrict__ wl)
{
    const int i = blockIdx.x * blockDim.x + threadIdx.x;
    const int fam = i >> 18;
    const int off = i & 262143;
    float v = wp.p[fam][off];
    __nv_bfloat16 h = __float2bfloat16_rn(v);
    wh[i] = h;
    wl[i] = __float2bfloat16_rn(v - __bfloat162float(h));
}

// ===========================================================================
// bf16-split TC GEMM (R4-proven config, plain epilogue):
//   C[M,256] = op(A)[M,256] @ W[256,256]^T + bias
//   op(A)=A (BNRELU=false) | relu(A*bnsc[k]+bnsh[k]) (BNRELU=true)
// B from pre-split bf16 weights via cp.async.
// CTA 128x128, 8 warps (2Mx4N), warp 64x32, BK=16, 2-stage pipeline,
// static smem 48KB, __launch_bounds__(256,2) -> 2 CTAs/SM.
// Stage layout (48B row stride): Ah+0 Al+6144 Bh+12288 Bl+18432 ; 24576B.
// ===========================================================================
#define STAGE_B 24576

template<bool BNRELU>
__global__ __launch_bounds__(256, 2)
void mma_gemm_kernel(const float* __restrict__ A,
                     const __nv_bfloat16* __restrict__ Wh,
                     const __nv_bfloat16* __restrict__ Wl,
                     const float* __restrict__ bias,
                     const float* __restrict__ bnsc, const float* __restrict__ bnsh,
                     float* __restrict__ C)
{
    __shared__ char smem[2 * STAGE_B];
    const uint32_t sb = smem_u32(smem);

    const int tid  = threadIdx.x;
    const int lane = tid & 31;
    const int wid  = tid >> 5;
    const int warpM = wid >> 2;
    const int warpN = wid & 3;
    const int blockN = blockIdx.x * 128;
    const int blockM = blockIdx.y * 128;

    const uint32_t aoff = (uint32_t)((warpM * 64 + (lane & 15)) * 48 + (lane >> 4) * 16);
    const uint32_t boff = (uint32_t)((warpN * 32 + (lane & 7) + ((lane >> 4) & 1) * 8) * 48
                                     + ((lane >> 3) & 1) * 16);

    // A fp32 producer mapping
    const int prow = tid >> 2;          // 0..63 (+64)
    const int pq   = tid & 3;
    // B cp.async producer mapping
    const int brow = tid >> 1;          // 0..127
    const int bhf  = tid & 1;

    float acc[4][4][4];
    #pragma unroll
    for (int i = 0; i < 4; i++)
        #pragma unroll
        for (int j = 0; j < 4; j++)
            #pragma unroll
            for (int r = 0; r < 4; r++) acc[i][j][r] = 0.f;

    auto issue_b = [&](uint32_t stage, int kt) {
        const uint32_t d = stage + (uint32_t)(brow * 48 + bhf * 16);
        const int so = (blockN + brow) * DIM + kt + bhf * 8;
        cpasync16(sb + d + 12288, Wh + so);
        cpasync16(sb + d + 18432, Wl + so);
    };
    auto st_a = [&](uint32_t stage, int kt, const float4* g) {
        #pragma unroll
        for (int j = 0; j < 2; j++) {
            float4 a = g[j];
            if (BNRELU) {
                const float4 sc = *(const float4*)&bnsc[kt + pq * 4];
                const float4 sh = *(const float4*)&bnsh[kt + pq * 4];
                a.x = fmaxf(fmaf(a.x, sc.x, sh.x), 0.f);
                a.y = fmaxf(fmaf(a.y, sc.y, sh.y), 0.f);
                a.z = fmaxf(fmaf(a.z, sc.z, sh.z), 0.f);
                a.w = fmaxf(fmaf(a.w, sc.w, sh.w), 0.f);
            }
            float h0,l0,h1,l1,h2,l2,h3,l3;
            split_bf16(a.x, h0, l0); split_bf16(a.y, h1, l1);
            split_bf16(a.z, h2, l2); split_bf16(a.w, h3, l3);
            const uint32_t dst = stage + (uint32_t)((prow + j * 64) * 48 + pq * 8);
            *(uint2*)(smem + dst)        = make_uint2(pack_bf16(h0, h1), pack_bf16(h2, h3));
            *(uint2*)(smem + dst + 6144) = make_uint2(pack_bf16(l0, l1), pack_bf16(l2, l3));
        }
    };

    // ---- prologue: stage 0 ----
    issue_b(0, 0);
    cpasync_commit();
    {
        float4 g0[2];
        #pragma unroll
        for (int j = 0; j < 2; j++)
            g0[j] = *(const float4*)&A[(blockM + prow + j * 64) * DIM + pq * 4];
        st_a(0, 0, g0);
    }
    cpasync_wait0();
    __syncthreads();

    #pragma unroll 1
    for (int ks = 0; ks < 16; ks++) {
        const uint32_t cur = (uint32_t)(ks & 1) * STAGE_B;
        const uint32_t nxt = (uint32_t)((ks + 1) & 1) * STAGE_B;

        float4 gA[2];
        if (ks < 15) {
            const int kt = (ks + 1) * 16;
            issue_b(nxt, kt);
            cpasync_commit();
            #pragma unroll
            for (int j = 0; j < 2; j++)
                gA[j] = *(const float4*)&A[(blockM + prow + j * 64) * DIM + kt + pq * 4];
        }

        // ---- compute current stage: 3 split terms ----
        {
            uint32_t bhr[4][2];
            #pragma unroll
            for (int j = 0; j < 2; j++) {
                uint32_t t[4];
                ldsm4(t, sb + cur + 12288 + boff + (uint32_t)(j * 768));
                bhr[2*j][0] = t[0]; bhr[2*j][1] = t[1];
                bhr[2*j+1][0] = t[2]; bhr[2*j+1][1] = t[3];
            }
            uint32_t af[4][4];
            #pragma unroll
            for (int mt = 0; mt < 4; mt++)
                ldsm4(af[mt], sb + cur + aoff + (uint32_t)(mt * 768));
            #pragma unroll
            for (int mt = 0; mt < 4; mt++)
                #pragma unroll
                for (int nt = 0; nt < 4; nt++)
                    mma_bf16(acc[mt][nt], af[mt], bhr[nt][0], bhr[nt][1]);   // ah*bh

            uint32_t blr[4][2];
            #pragma unroll
            for (int j = 0; j < 2; j++) {
                uint32_t t[4];
                ldsm4(t, sb + cur + 18432 + boff + (uint32_t)(j * 768));
                blr[2*j][0] = t[0]; blr[2*j][1] = t[1];
                blr[2*j+1][0] = t[2]; blr[2*j+1][1] = t[3];
            }
            #pragma unroll
            for (int mt = 0; mt < 4; mt++)
                #pragma unroll
                for (int nt = 0; nt < 4; nt++)
                    mma_bf16(acc[mt][nt], af[mt], blr[nt][0], blr[nt][1]); // ah*bl

            #pragma unroll
            for (int mt = 0; mt < 4; mt++)
                ldsm4(af[mt], sb + cur + 6144 + aoff + (uint32_t)(mt * 768));
            #pragma unroll
            for (int mt = 0; mt < 4; mt++)
                #pragma unroll
                for (int nt = 0; nt < 4; nt++)
                    mma_bf16(acc[mt][nt], af[mt], bhr[nt][0], bhr[nt][1]);   // al*bh
        }

        if (ks < 15) st_a(nxt, (ks + 1) * 16, gA);
        cpasync_wait0();
        __syncthreads();
    }

    // ---- epilogue: bias add + direct stores ----
    #pragma unroll
    for (int nt = 0; nt < 4; nt++) {
        const int n0 = blockN + warpN * 32 + nt * 8 + (lane & 3) * 2;
        const float2 bb = *(const float2*)&bias[n0];
        #pragma unroll
        for (int mt = 0; mt < 4; mt++) {
            const int m0 = blockM + warpM * 64 + mt * 16 + (lane >> 2);
            float2 o0 = make_float2(acc[mt][nt][0] + bb.x, acc[mt][nt][1] + bb.y);
            float2 o1 = make_float2(acc[mt][nt][2] + bb.x, acc[mt][nt][3] + bb.y);
            *(float2*)&C[m0 * DIM + n0]       = o0;
            *(float2*)&C[(m0 + 8) * DIM + n0] = o1;
        }
    }
}

// ---------------------------------------------------------------------------
// W = K - Q, plus per-channel sum / sumsq  (thread = channel, block strides rows)
__global__ void sub_stats_kernel(const float* __restrict__ Kx, const float* __restrict__ Qx,
                                 float* __restrict__ Wout, float* __restrict__ stats)
{
    const int d = threadIdx.x;
    float s1 = 0.f, s2 = 0.f;
    #pragma unroll 4
    for (int r = blockIdx.x; r < MROWS; r += gridDim.x) {
        const int i = r * DIM + d;
        float w = Kx[i] - Qx[i];
        Wout[i] = w;
        s1 += w; s2 += w * w;
    }
    atomicAdd(&stats[d], s1);
    atomicAdd(&stats[DIM + d], s2);
}

__global__ void stats_kernel(const float* __restrict__ X, float* __restrict__ stats)
{
    const int d = threadIdx.x;
    float s1 = 0.f, s2 = 0.f;
    #pragma unroll 4
    for (int r = blockIdx.x; r < MROWS; r += gridDim.x) {
        float w = X[r * DIM + d];
        s1 += w; s2 += w * w;
    }
    atomicAdd(&stats[d], s1);
    atomicAdd(&stats[DIM + d], s2);
}

// bn_finalize: consume stats -> (scale, shift), then re-zero stats buffer.
__global__ void bn_finalize_kernel(float* __restrict__ stats,
                                   const float* __restrict__ gamma,
                                   const float* __restrict__ beta,
                                   float* __restrict__ sc, float* __restrict__ sh)
{
    const int d = threadIdx.x;
    const float inv = 1.f / (float)MROWS;
    float mean = stats[d] * inv;
    float var  = stats[DIM + d] * inv - mean * mean;
    float r    = rsqrtf(var + 1e-5f);
    float s    = gamma[d] * r;
    sc[d] = s;
    sh[d] = beta[d] - mean * s;
    stats[d] = 0.f;
    stats[DIM + d] = 0.f;
}

// ---------------------------------------------------------------------------
__global__ void softmax_wsum_kernel(const float* __restrict__ Wm,
                                    const float* __restrict__ V,
                                    float* __restrict__ out)
{
    const int b    = blockIdx.x >> 3;
    const int lane = threadIdx.x & 31;
    const int w    = threadIdx.x >> 5;
    const int d    = ((blockIdx.x & 7) << 5) + lane;
    const int BD   = BATCH * DIM;
    const int base = b * DIM + d;

    const float NEG_INF = __int_as_float(0xff800000u);
    float m = NEG_INF, Z = 0.f, acc = 0.f;
    const int s0 = w * (SEQ / 8);
    for (int s = s0; s < s0 + SEQ / 8; s++) {
        const int idx = s * BD + base;
        float x  = Wm[idx];
        float vv = V[idx];
        if (x > m) {
            float c = __expf(m - x);
            Z   = Z * c + 1.f;
            acc = acc * c + vv;
            m = x;
        } else {
            float e = __expf(x - m);
            Z   += e;
            acc += e * vv;
        }
    }
    __shared__ float sm[8][32], sz[8][32], sa[8][32];
    sm[w][lane] = m; sz[w][lane] = Z; sa[w][lane] = acc;
    __syncthreads();
    if (w == 0) {
        float M = NEG_INF;
        #pragma unroll
        for (int j = 0; j < 8; j++) M = fmaxf(M, sm[j][lane]);
        float Zt = 0.f, At = 0.f;
        #pragma unroll
        for (int j = 0; j < 8; j++) {
            float c = __expf(sm[j][lane] - M);
            Zt += sz[j][lane] * c;
            At += sa[j][lane] * c;
        }
        out[base] = At / Zt;
    }
}

__global__ void pack_kernel(const float* __restrict__ ho, float* __restrict__ x0)
{
    const int i = blockIdx.x * blockDim.x + threadIdx.x;
    const int b = i >> 10;
    const int c = i & 1023;
    const int h = c >> 8;
    const int d = c & 255;
    x0[i] = ho[h * (BATCH * DIM) + b * DIM + d];
}

template<bool RELU, int K>
__global__ void smallgemm_kernel(const float* __restrict__ X, const float* __restrict__ Wt,
                                 const float* __restrict__ bias, float* __restrict__ C)
{
    __shared__ float Xs[32][257];
    __shared__ float Ws[8][257];
    const int tid = threadIdx.x;
    const int b  = tid & 31;
    const int nl = tid >> 5;
    const int n  = blockIdx.x * 8 + nl;
    float acc = 0.f;
    for (int k0 = 0; k0 < K; k0 += 256) {
        #pragma unroll
        for (int j = 0; j < 8; j++)
            Ws[j][tid] = Wt[(blockIdx.x * 8 + j) * K + k0 + tid];
        #pragma unroll
        for (int j = 0; j < 32; j++)
            Xs[j][tid] = X[j * K + k0 + tid];
        __syncthreads();
        #pragma unroll 8
        for (int kk = 0; kk < 256; kk++) acc += Xs[b][kk] * Ws[nl][kk];
        __syncthreads();
    }
    float val = acc + bias[n];
    if (RELU) val = fmaxf(val, 0.f);
    C[b * DIM + n] = val;
}

// ---------------------------------------------------------------------------
extern "C" void kernel_launch(void* const* d_in, const int* in_sizes, int n_in,
                              void* d_out, int out_size)
{
    const float* q   = (const float*)d_in[0];
    const float* k   = (const float*)d_in[1];
    const float* v   = (const float*)d_in[2];
    const float* wq  = (const float*)d_in[3];
    const float* bq  = (const float*)d_in[4];
    const float* wk  = (const float*)d_in[5];
    const float* bk  = (const float*)d_in[6];
    const float* wv  = (const float*)d_in[7];
    const float* bv  = (const float*)d_in[8];
    const float* g1  = (const float*)d_in[9];
    const float* be1 = (const float*)d_in[10];
    const float* wl1 = (const float*)d_in[11];
    const float* bl1 = (const float*)d_in[12];
    const float* g2  = (const float*)d_in[13];
    const float* be2 = (const float*)d_in[14];
    const float* wl2 = (const float*)d_in[15];
    const float* bl2 = (const float*)d_in[16];
    const float* mw0 = (const float*)d_in[17];
    const float* mb0 = (const float*)d_in[18];
    const float* mw1 = (const float*)d_in[19];
    const float* mb1 = (const float*)d_in[20];
    const float* mw2 = (const float*)d_in[21];
    const float* mb2 = (const float*)d_in[22];

    float* buf;   cudaGetSymbolAddress((void**)&buf,   g_buf);
    float* stats; cudaGetSymbolAddress((void**)&stats, g_stats);
    float* bnsc;  cudaGetSymbolAddress((void**)&bnsc,  g_bnscale);
    float* bnsh;  cudaGetSymbolAddress((void**)&bnsh,  g_bnshift);
    float* ho;    cudaGetSymbolAddress((void**)&ho,    g_headout);
    float* x0;    cudaGetSymbolAddress((void**)&x0,    g_x0);
    float* x1;    cudaGetSymbolAddress((void**)&x1,    g_x1);
    float* x2;    cudaGetSymbolAddress((void**)&x2,    g_x2);
    __nv_bfloat16* wh; cudaGetSymbolAddress((void**)&wh, g_wh);
    __nv_bfloat16* wl; cudaGetSymbolAddress((void**)&wl, g_wl);

    float* Qb[2] = { buf + (size_t)0*NBUF, buf + (size_t)1*NBUF };
    float* Kb[2] = { buf + (size_t)2*NBUF, buf + (size_t)3*NBUF };
    float* Vb[2] = { buf + (size_t)4*NBUF, buf + (size_t)5*NBUF };
    float* Wa    =   buf + (size_t)6*NBUF;
    float* Wb    =   buf + (size_t)7*NBUF;

    // split all weights once per replay
    WPtrs wp; wp.p[0] = wq; wp.p[1] = wk; wp.p[2] = wv; wp.p[3] = wl1; wp.p[4] = wl2;
    wsplit_kernel<<<5 * HEADS * DIM * DIM / 256, 256>>>(wp, wh, wl);

    const int WSZ = DIM * DIM;
    dim3 gg(DIM / 128, MROWS / 128);   // (2, 512)

    const float* Qc = q; const float* Kc = k; const float* Vc = v;
    for (int i = 0; i < HEADS; i++) {
        float* Qn = Qb[i & 1]; float* Kn = Kb[i & 1]; float* Vn = Vb[i & 1];
        const __nv_bfloat16 *qh = wh + (0*HEADS+i)*WSZ, *ql = wl + (0*HEADS+i)*WSZ;
        const __nv_bfloat16 *kh = wh + (1*HEADS+i)*WSZ, *kl = wl + (1*HEADS+i)*WSZ;
        const __nv_bfloat16 *vh = wh + (2*HEADS+i)*WSZ, *vl = wl + (2*HEADS+i)*WSZ;
        const __nv_bfloat16 *l1h= wh + (3*HEADS+i)*WSZ, *l1l= wl + (3*HEADS+i)*WSZ;
        const __nv_bfloat16 *l2h= wh + (4*HEADS+i)*WSZ, *l2l= wl + (4*HEADS+i)*WSZ;

        mma_gemm_kernel<false><<<gg, 256>>>(Qc, qh, ql, bq + i*DIM, nullptr, nullptr, Qn);
        mma_gemm_kernel<false><<<gg, 256>>>(Kc, kh, kl, bk + i*DIM, nullptr, nullptr, Kn);
        mma_gemm_kernel<false><<<gg, 256>>>(Vc, vh, vl, bv + i*DIM, nullptr, nullptr, Vn);

        sub_stats_kernel<<<2048, DIM>>>(Kn, Qn, Wa, stats);
        bn_finalize_kernel<<<1, DIM>>>(stats, g1 + i*DIM, be1 + i*DIM, bnsc, bnsh);

        mma_gemm_kernel<true><<<gg, 256>>>(Wa, l1h, l1l, bl1 + i*DIM, bnsc, bnsh, Wb);

        stats_kernel<<<2048, DIM>>>(Wb, stats);
        bn_finalize_kernel<<<1, DIM>>>(stats, g2 + i*DIM, be2 + i*DIM, bnsc, bnsh);

        mma_gemm_kernel<true><<<gg, 256>>>(Wb, l2h, l2l, bl2 + i*DIM, bnsc, bnsh, Wa);

        softmax_wsum_kernel<<<BATCH * (DIM / 32), 256>>>(Wa, Vn, ho + i*BATCH*DIM);

        Qc = Qn; Kc = Kn; Vc = Vn;
    }

    pack_kernel<<<32, 1024>>>(ho, x0);
    smallgemm_kernel<true,  HEADS*DIM><<<DIM / 8, 256>>>(x0, mw0, mb0, x1);
    smallgemm_kernel<true,  DIM      ><<<DIM / 8, 256>>>(x1, mw1, mb1, x2);
    smallgemm_kernel<false, DIM      ><<<DIM / 8, 256>>>(x2, mw2, mb2, (float*)d_out);
}